// round 1
// baseline (speedup 1.0000x reference)
#include <cuda_runtime.h>

#define TT  15
#define C1I 6
#define HI  224
#define WI  224
#define C1O 30
#define HP  114
#define WP  114
#define C2O 240
#define HO  112
#define WO  112

// Padded, pooled layer-1 spike map: (T, 30, 114, 114), border = 0 (pad 1).
__device__ float g_spk1[(size_t)TT * C1O * HP * WP];

// ---------------------------------------------------------------------------
// Kernel 1: conv1 (5x5, pad 2) + fire(15) + maxpool 2x2 + pad 1, fused.
// Each block: 16x16 pooled pixels for one t, all 30 out-channels.
// Key identity: pooled spike = (max of the 4 conv potentials) > 15.
// ---------------------------------------------------------------------------
__global__ __launch_bounds__(256) void k_conv1(const float* __restrict__ in,
                                               const float* __restrict__ w1) {
    extern __shared__ float smem[];
    float* sIn = smem;                 // [6][36][37]
    float* sW  = smem + 6 * 36 * 37;   // [30*6*25] = 4500

    const int t   = blockIdx.z;
    const int X0  = blockIdx.x * 16;   // pooled-x base
    const int Y0  = blockIdx.y * 16;   // pooled-y base
    const int tid = threadIdx.x;

    for (int i = tid; i < 4500; i += 256) sW[i] = w1[i];

    // Input region: rows 2*Y0-2 .. 2*Y0+33, cols 2*X0-2 .. 2*X0+33 (36x36/ch)
    const float* inT = in + (size_t)t * (C1I * HI * WI);
    for (int i = tid; i < 6 * 36 * 36; i += 256) {
        int c  = i % 36;
        int r  = (i / 36) % 36;
        int ic = i / (36 * 36);
        int gy = 2 * Y0 - 2 + r;
        int gx = 2 * X0 - 2 + c;
        float v = 0.0f;
        if ((unsigned)gy < (unsigned)HI && (unsigned)gx < (unsigned)WI)
            v = inT[(ic * HI + gy) * WI + gx];
        sIn[(ic * 36 + r) * 37 + c] = v;
    }
    __syncthreads();

    const int tx = tid & 15;
    const int ty = tid >> 4;
    float* outp = g_spk1 + (size_t)t * C1O * HP * WP
                + (size_t)(Y0 + ty + 1) * WP + (X0 + tx + 1);

    // 30 out-channels in 5 groups of 6
    for (int cg = 0; cg < 5; cg++) {
        float pot[6][4];
#pragma unroll
        for (int u = 0; u < 6; u++)
#pragma unroll
            for (int q = 0; q < 4; q++) pot[u][q] = 0.0f;

        for (int ic = 0; ic < 6; ic++) {
            float p[6][6];   // register patch covering the 2x2 conv window + 5x5 taps
#pragma unroll
            for (int r = 0; r < 6; r++)
#pragma unroll
                for (int c = 0; c < 6; c++)
                    p[r][c] = sIn[(ic * 36 + 2 * ty + r) * 37 + 2 * tx + c];

#pragma unroll
            for (int u = 0; u < 6; u++) {
                const float* w = sW + ((cg * 6 + u) * 6 + ic) * 25;
#pragma unroll
                for (int kh = 0; kh < 5; kh++)
#pragma unroll
                    for (int kw = 0; kw < 5; kw++) {
                        float wv = w[kh * 5 + kw];
                        pot[u][0] = fmaf(p[kh    ][kw    ], wv, pot[u][0]);
                        pot[u][1] = fmaf(p[kh    ][kw + 1], wv, pot[u][1]);
                        pot[u][2] = fmaf(p[kh + 1][kw    ], wv, pot[u][2]);
                        pot[u][3] = fmaf(p[kh + 1][kw + 1], wv, pot[u][3]);
                    }
            }
        }
#pragma unroll
        for (int u = 0; u < 6; u++) {
            float m = fmaxf(fmaxf(pot[u][0], pot[u][1]),
                            fmaxf(pot[u][2], pot[u][3]));
            outp[(size_t)(cg * 6 + u) * HP * WP] = (m > 15.0f) ? 1.0f : 0.0f;
        }
    }
}

// ---------------------------------------------------------------------------
// Kernel 2: conv2 (3x3, 30->240) + fire(10), write spk and pot.
// Block: 16x16 spatial tile, 16 out-channels. Thread: 4 px (x) * 4 oc.
// ---------------------------------------------------------------------------
__global__ __launch_bounds__(256) void k_conv2(const float* __restrict__ w2,
                                               float* __restrict__ spk,
                                               float* __restrict__ pot) {
    extern __shared__ float smem[];
    float* sIn = smem;                  // [30][18][19]
    float* sW  = smem + 30 * 18 * 19;   // [16*270]

    const int t   = blockIdx.z / 15;
    const int ocb = (blockIdx.z % 15) * 16;
    const int X0  = blockIdx.x * 16;
    const int Y0  = blockIdx.y * 16;
    const int tid = threadIdx.x;

    // Weights for 16 out-channels: contiguous chunk of w2
    const float* wsrc = w2 + (size_t)ocb * 270;
    for (int i = tid; i < 16 * 270; i += 256) sW[i] = wsrc[i];

    // Input tile: 30ch x 18x18 from padded pooled spike map
    const float* sp = g_spk1 + (size_t)t * (C1O * HP * WP);
    for (int i = tid; i < 30 * 18 * 18; i += 256) {
        int c  = i % 18;
        int r  = (i / 18) % 18;
        int ic = i / (18 * 18);
        sIn[(ic * 18 + r) * 19 + c] = sp[(ic * HP + Y0 + r) * WP + X0 + c];
    }
    __syncthreads();

    const int qx = tid & 3;          // 4 threads across x, 4 px each
    const int ty = (tid >> 2) & 15;  // 16 rows
    const int g  = tid >> 6;         // 4 oc-groups of 4

    float acc[4][4];
#pragma unroll
    for (int u = 0; u < 4; u++)
#pragma unroll
        for (int p = 0; p < 4; p++) acc[u][p] = 0.0f;

    for (int ic = 0; ic < 30; ic++) {
#pragma unroll
        for (int kh = 0; kh < 3; kh++) {
            float v[6];
            const float* row = sIn + (ic * 18 + ty + kh) * 19 + 4 * qx;
#pragma unroll
            for (int j = 0; j < 6; j++) v[j] = row[j];
#pragma unroll
            for (int u = 0; u < 4; u++) {
                const float* w = sW + (g * 4 + u) * 270 + ic * 9 + kh * 3;
                float w0 = w[0], w1 = w[1], w2v = w[2];
#pragma unroll
                for (int p = 0; p < 4; p++) {
                    acc[u][p] = fmaf(v[p],     w0,  acc[u][p]);
                    acc[u][p] = fmaf(v[p + 1], w1,  acc[u][p]);
                    acc[u][p] = fmaf(v[p + 2], w2v, acc[u][p]);
                }
            }
        }
    }

    const int y = Y0 + ty;
    const int x = X0 + 4 * qx;
#pragma unroll
    for (int u = 0; u < 4; u++) {
        int oc = ocb + g * 4 + u;
        size_t base = (((size_t)t * C2O + oc) * HO + y) * WO + x;
        float a0 = acc[u][0], a1 = acc[u][1], a2 = acc[u][2], a3 = acc[u][3];
        float4 s4, p4;
        s4.x = a0 > 10.0f ? 1.0f : 0.0f;  p4.x = a0 > 10.0f ? a0 : 0.0f;
        s4.y = a1 > 10.0f ? 1.0f : 0.0f;  p4.y = a1 > 10.0f ? a1 : 0.0f;
        s4.z = a2 > 10.0f ? 1.0f : 0.0f;  p4.z = a2 > 10.0f ? a2 : 0.0f;
        s4.w = a3 > 10.0f ? 1.0f : 0.0f;  p4.w = a3 > 10.0f ? a3 : 0.0f;
        *reinterpret_cast<float4*>(spk + base) = s4;
        *reinterpret_cast<float4*>(pot + base) = p4;
    }
}

// ---------------------------------------------------------------------------
extern "C" void kernel_launch(void* const* d_in, const int* in_sizes, int n_in,
                              void* d_out, int out_size) {
    const float* in = (const float*)d_in[0];
    const float* w1 = (const float*)d_in[1];
    const float* w2 = (const float*)d_in[2];
    // d_in[3] = max_layer, always 2 in this problem.

    float* spk = (float*)d_out;
    const size_t n2 = (size_t)TT * C2O * HO * WO;
    float* pot = spk + n2;

    // Zero the scratch spike map (gives us the pad-1 border for free).
    void* sp1 = nullptr;
    cudaGetSymbolAddress(&sp1, g_spk1);
    cudaMemsetAsync(sp1, 0, sizeof(g_spk1), 0);

    const int smem1 = (6 * 36 * 37 + 4500) * (int)sizeof(float);       // 49,968 B
    const int smem2 = (30 * 18 * 19 + 16 * 270) * (int)sizeof(float);  // 58,320 B
    cudaFuncSetAttribute(k_conv1, cudaFuncAttributeMaxDynamicSharedMemorySize, smem1);
    cudaFuncSetAttribute(k_conv2, cudaFuncAttributeMaxDynamicSharedMemorySize, smem2);

    k_conv1<<<dim3(7, 7, TT), 256, smem1>>>(in, w1);
    k_conv2<<<dim3(7, 7, TT * 15), 256, smem2>>>(w2, spk, pot);
}